// round 12
// baseline (speedup 1.0000x reference)
#include <cuda_runtime.h>
#include <cstdint>

namespace {

constexpr int Bsz  = 128;
constexpr int L1   = 1024;
constexpr int L2n  = 128;
constexpr int H2   = 600;
constexpr int KPAD = 608;           // 19 * 32
constexpr int KT   = 32;            // K per stage tile
constexpr int T    = KPAD / KT;     // 19
constexpr int S    = 3;             // pipeline stages
constexpr int PRE  = 2;

constexpr int STRD = 36;            // smem row stride (floats); 144B rows
constexpr int A_ROWS = 128, B_ROWS = 128;
constexpr int STAGE_BYTES = (A_ROWS + B_ROWS) * STRD * 4;    // 36864
constexpr int SM_STAGE_B  = 512;                             // byte offset of stage 0
constexpr int SMEM_TOTAL  = SM_STAGE_B + S * STAGE_BYTES;    // 111104 (x2 per SM)

__device__ float g_bscaled[(size_t)Bsz * L2n * KPAD];        // ~39.8MB scratch
__device__ float g_sasp[Bsz * L2n];

__device__ __forceinline__ uint32_t cvta_s(const void* p) {
    uint32_t a;
    asm("{ .reg .u64 t; cvta.to.shared.u64 t, %1; cvt.u32.u64 %0, t; }"
        : "=r"(a) : "l"(p));
    return a;
}
__device__ __forceinline__ void cp16(uint32_t d, const void* s) {
    asm volatile("cp.async.cg.shared.global [%0], [%1], 16;" :: "r"(d), "l"(s));
}
__device__ __forceinline__ void cp16z(uint32_t d, const void* s) {
    asm volatile("cp.async.cg.shared.global [%0], [%1], 16, 0;" :: "r"(d), "l"(s));
}
#define CPCOMMIT() asm volatile("cp.async.commit_group;" ::: "memory")
#define CPWAIT(n)  asm volatile("cp.async.wait_group %0;" :: "n"(n) : "memory")

// NON-volatile ldmatrix: pure function of the address -> ptxas may software-
// pipeline these across kk groups. Ordering vs. the stage barrier is enforced
// by the dep-anchored address (see mainloop), not by volatility.
__device__ __forceinline__ void ldsm4(uint32_t& r0, uint32_t& r1, uint32_t& r2,
                                      uint32_t& r3, uint32_t a) {
    asm("ldmatrix.sync.aligned.m8n8.x4.shared.b16 {%0,%1,%2,%3}, [%4];"
        : "=r"(r0), "=r"(r1), "=r"(r2), "=r"(r3) : "r"(a));
}
__device__ __forceinline__ void mma8(float& d0, float& d1, float& d2, float& d3,
                                     uint32_t a0, uint32_t a1, uint32_t a2, uint32_t a3,
                                     uint32_t b0, uint32_t b1) {
    asm volatile(
        "mma.sync.aligned.m16n8k8.row.col.f32.tf32.tf32.f32 "
        "{%0,%1,%2,%3}, {%4,%5,%6,%7}, {%8,%9}, {%0,%1,%2,%3};"
        : "+f"(d0), "+f"(d1), "+f"(d2), "+f"(d3)
        : "r"(a0), "r"(a1), "r"(a2), "r"(a3), "r"(b0), "r"(b1));
}

// ---- pre-pass: B' = rn_tf32(w3*asp + w1) [K pad to 608], s_asp = asp.w2 ----
__global__ void __launch_bounds__(256) prep_kernel(const float* __restrict__ asp,
                                                   const float* __restrict__ wu) {
    __shared__ float w[1800];
    const int tid = threadIdx.x;
    for (int i = tid; i < 1800; i += 256) w[i] = wu[i];
    __syncthreads();

    const int lane = tid & 31;
    const int row  = blockIdx.x * 8 + (tid >> 5);
    const float* r = asp + (size_t)row * H2;
    float* o = g_bscaled + (size_t)row * KPAD;

    float4 av = {0.f, 0.f, 0.f, 0.f};
    for (int c = lane; c < 150; c += 32) {
        const int k = c * 4;
        const float4 a = *(const float4*)(r + k);
        float4 v;
        v.x = fmaf(a.x, w[1200 + k + 0], w[k + 0]);
        v.y = fmaf(a.y, w[1200 + k + 1], w[k + 1]);
        v.z = fmaf(a.z, w[1200 + k + 2], w[k + 2]);
        v.w = fmaf(a.w, w[1200 + k + 3], w[k + 3]);
        asm("cvt.rna.tf32.f32 %0, %1;" : "=f"(v.x) : "f"(v.x));
        asm("cvt.rna.tf32.f32 %0, %1;" : "=f"(v.y) : "f"(v.y));
        asm("cvt.rna.tf32.f32 %0, %1;" : "=f"(v.z) : "f"(v.z));
        asm("cvt.rna.tf32.f32 %0, %1;" : "=f"(v.w) : "f"(v.w));
        *(float4*)(o + k) = v;
        av.x = fmaf(a.x, w[600 + k + 0], av.x);
        av.y = fmaf(a.y, w[600 + k + 1], av.y);
        av.z = fmaf(a.z, w[600 + k + 2], av.z);
        av.w = fmaf(a.w, w[600 + k + 3], av.w);
    }
    if (lane < 2) *(float4*)(o + 600 + 4 * lane) = make_float4(0.f, 0.f, 0.f, 0.f);

    float acc = (av.x + av.y) + (av.z + av.w);
    #pragma unroll
    for (int off = 16; off; off >>= 1) acc += __shfl_xor_sync(0xffffffffu, acc, off);
    if (lane == 0) g_sasp[row] = acc;
}

// ---- main GEMM: mma.sync tf32, CTA 128x128, 8 warps (64x32 tiles), 2 CTA/SM ----
__global__ void __launch_bounds__(256, 2)
gemm_kernel(const float* __restrict__ ctx, float* __restrict__ out) {
    extern __shared__ float sm[];
    const uint32_t sb = cvta_s(sm);
    const int tid  = threadIdx.x;
    const int lane = tid & 31;
    const int wid  = tid >> 5;
    const int wm = wid >> 2, wn = wid & 3;     // 2 x 4 warp grid
    const int m0 = wm * 64, n0 = wn * 32;
    const int g  = lane >> 2;
    const int tg = lane & 3;
    const int mt = blockIdx.x, b = blockIdx.y;

    const float* actx = ctx + (size_t)(b * L1 + mt * 128) * H2;
    const float* absc = g_bscaled + (size_t)b * L2n * KPAD;

    if (tid < 128) sm[tid] = g_sasp[b * L2n + tid];

    float acc[4][4][4];
    #pragma unroll
    for (int i = 0; i < 4; i++)
        #pragma unroll
        for (int j = 0; j < 4; j++)
            #pragma unroll
            for (int q = 0; q < 4; q++) acc[i][j][q] = 0.f;

    // ldmatrix per-lane address offsets (bytes, within a stage)
    const uint32_t aoff = (uint32_t)((m0 + (lane & 15)) * STRD * 4 + ((lane >> 4) << 4));
    const uint32_t boff = (uint32_t)((A_ROWS + n0 + ((lane >> 4) << 3) + (lane & 7)) * STRD * 4
                                     + (((lane >> 3) & 1) << 4));

    // stage filler: 2048 16B chunks, 8 per thread
    auto issue = [&](int t) {
        const int k0 = t * KT;
        const uint32_t st = sb + SM_STAGE_B + (t % S) * STAGE_BYTES;
        #pragma unroll
        for (int i = 0; i < 8; i++) {
            const int f = tid + i * 256;
            const int r = f >> 3, u = f & 7;
            if (r < 128) {
                const uint32_t d = st + (uint32_t)(r * STRD * 4 + u * 16);
                if (k0 + u * 4 < H2) cp16(d, actx + (size_t)r * H2 + k0 + u * 4);
                else                 cp16z(d, actx);
            } else {
                const int rb = r - 128;
                const uint32_t d = st + (uint32_t)((A_ROWS + rb) * STRD * 4 + u * 16);
                cp16(d, absc + (size_t)rb * KPAD + k0 + u * 4);
            }
        }
    };

    #pragma unroll
    for (int t = 0; t < PRE; t++) { issue(t); CPCOMMIT(); }

    for (int t = 0; t < T; t++) {
        CPWAIT(PRE - 1);
        __syncthreads();

        // dep anchor: volatile (w/ memory clobber) cannot move above the
        // barrier; all ldsm addresses depend on 'dep', so no ldsm can hoist
        // above the barrier either. mma8 stays volatile, anchoring the tail.
        uint32_t dep;
        asm volatile("mov.u32 %0, 0;" : "=r"(dep) :: "memory");

        const uint32_t stg = sb + SM_STAGE_B + (t % S) * STAGE_BYTES + dep;
        const uint32_t aB = stg + aoff;
        const uint32_t bB = stg + boff;

        #pragma unroll
        for (int kk = 0; kk < 4; kk++) {
            uint32_t af[4][4], bf[4][2];
            #pragma unroll
            for (int im = 0; im < 4; im++)
                ldsm4(af[im][0], af[im][1], af[im][2], af[im][3],
                      aB + im * 16 * STRD * 4 + kk * 32);
            #pragma unroll
            for (int p = 0; p < 2; p++)
                ldsm4(bf[2 * p][0], bf[2 * p][1], bf[2 * p + 1][0], bf[2 * p + 1][1],
                      bB + p * 16 * STRD * 4 + kk * 32);
            #pragma unroll
            for (int im = 0; im < 4; im++)
                #pragma unroll
                for (int in = 0; in < 4; in++)
                    mma8(acc[im][in][0], acc[im][in][1], acc[im][in][2], acc[im][in][3],
                         af[im][0], af[im][1], af[im][2], af[im][3],
                         bf[in][0], bf[in][1]);
        }

        if (t + PRE < T) issue(t + PRE);
        CPCOMMIT();
    }

    // ---- epilogue: add s_asp, store float2 per fragment half ----
    float* outb = out + (size_t)(b * L1 + mt * 128) * L2n;
    #pragma unroll
    for (int im = 0; im < 4; im++) {
        const int r0 = m0 + im * 16 + g;
        #pragma unroll
        for (int in = 0; in < 4; in++) {
            const int c = n0 + in * 8 + 2 * tg;
            const float s0 = sm[c], s1 = sm[c + 1];
            float2 v0 = { acc[im][in][0] + s0, acc[im][in][1] + s1 };
            float2 v1 = { acc[im][in][2] + s0, acc[im][in][3] + s1 };
            *(float2*)(outb + (size_t)r0 * L2n + c)       = v0;
            *(float2*)(outb + (size_t)(r0 + 8) * L2n + c) = v1;
        }
    }
}

}  // namespace

extern "C" void kernel_launch(void* const* d_in, const int* in_sizes, int n_in,
                              void* d_out, int out_size) {
    const float* ctx = nullptr;
    const float* asp = nullptr;
    const float* wu  = nullptr;
    for (int i = 0; i < n_in; i++) {
        const long sz = (long)in_sizes[i];
        if (sz == (long)Bsz * L1 * H2)       ctx = (const float*)d_in[i];
        else if (sz == (long)Bsz * L2n * H2) asp = (const float*)d_in[i];
        else if (sz == 3 * H2)               wu  = (const float*)d_in[i];
    }

    prep_kernel<<<(Bsz * L2n) / 8, 256>>>(asp, wu);

    cudaFuncSetAttribute(gemm_kernel, cudaFuncAttributeMaxDynamicSharedMemorySize,
                         SMEM_TOTAL);
    dim3 grid(L1 / 128, Bsz);
    gemm_kernel<<<grid, 256, SMEM_TOTAL>>>(ctx, (float*)d_out);
}